// round 6
// baseline (speedup 1.0000x reference)
#include <cuda_runtime.h>
#include <cuda_fp16.h>

#define NN 4096
#define ITERS 21            // 20 scan iterations + 1 last-iterate
#define GB 128              // main-kernel blocks (<= SM count -> co-resident, barrier-safe)
#define TB 256              // threads per block (8 warps)
#define RPB (NN / GB)       // 32 rows per block  (phase A ownership)
#define CPB (NN / GB)       // 32 cols per block  (phase B ownership)

// ---- device-global scratch (static allocation; no cudaMalloc allowed) ----
__device__ __align__(16) __half d_Kh[(size_t)NN * NN];  // K = param^2 in fp16 (32 MB, L2-resident)
__device__ float d_AF[NN];
__device__ float d_BF[NN];
__device__ unsigned int d_bar;  // monotone grid-barrier counter (never reset; wrap-safe for realistic replay counts)

// ---------------------------------------------------------------------------
// Software grid barrier. Safe because GB (128) <= #SMs so all blocks are
// resident. __threadfence() is gpu-scope -> emits CCTL.IVALL on sm_103a,
// invalidating L1 so post-barrier reads of d_AF/d_BF see other SMs' writes.
// ---------------------------------------------------------------------------
__device__ __forceinline__ void grid_sync() {
    __syncthreads();
    if (threadIdx.x == 0) {
        __threadfence();                                   // release (orders this block's stores)
        unsigned int nb  = gridDim.x;
        unsigned int old = atomicAdd(&d_bar, 1u);
        unsigned int gen = old - (old % nb) + nb;          // target count for this barrier instance
        while (*((volatile unsigned int*)&d_bar) < gen) { }
        __threadfence();                                   // acquire (CCTL.IVALL: flush stale L1)
    }
    __syncthreads();
}

// ---------------------------------------------------------------------------
// Setup: Kh = (float2half(param^2)). 8 elements per thread, exact coverage.
// ---------------------------------------------------------------------------
__global__ void setup_kernel(const float* __restrict__ param) {
    size_t base = ((size_t)blockIdx.x * blockDim.x + threadIdx.x) * 8;
    float4 p0 = *(const float4*)(param + base);
    float4 p1 = *(const float4*)(param + base + 4);
    __half2 hs[4];
    hs[0] = __floats2half2_rn(p0.x * p0.x, p0.y * p0.y);
    hs[1] = __floats2half2_rn(p0.z * p0.z, p0.w * p0.w);
    hs[2] = __floats2half2_rn(p1.x * p1.x, p1.y * p1.y);
    hs[3] = __floats2half2_rn(p1.z * p1.z, p1.w * p1.w);
    *reinterpret_cast<uint4*>(d_Kh + base) = *reinterpret_cast<uint4*>(hs);
}

// ---------------------------------------------------------------------------
// Persistent solver. Per iteration:
//   Phase A (rows r0..r0+31):  AF[r] = AT[r] / (1 + sum_j K[r][j]*BF[j])
//   Phase B (cols c0..c0+31):  BF[c] = BT[c] / (1 + sum_i AF[i]*K[i][c])
// One grid_sync after each phase. Then C = param^2 * AF[:,None] * BF[None,:].
// ---------------------------------------------------------------------------
__global__ void __launch_bounds__(TB) solve_kernel(
    const float* __restrict__ AT,
    const float* __restrict__ BT,
    const float* __restrict__ param,
    float* __restrict__ C)
{
    __shared__ float sBF[NN];        // phase A: BF (fp32); phase C: final BF
    __shared__ float sAF[NN];        // phase B: AF
    __shared__ float sPart[8 * 32];  // phase B cross-warp partials

    const int tid  = threadIdx.x;
    const int lane = tid & 31;
    const int w    = tid >> 5;       // warp 0..7
    const int b    = blockIdx.x;
    const int r0   = b * RPB;
    const int c0   = b * CPB;

    for (int it = 0; it < ITERS; ++it) {
        // ---------------- Phase A: row dots ----------------
        const float* bfsrc = (it == 0) ? BT : d_BF;   // BF_0 = BT
        for (int j = tid; j < NN; j += TB) sBF[j] = bfsrc[j];
        __syncthreads();

        #pragma unroll
        for (int rr = 0; rr < 4; ++rr) {              // 8 warps x 4 rows = 32 rows
            const int row = r0 + w * 4 + rr;
            const uint4*  krow = (const uint4*)(d_Kh + (size_t)row * NN);  // 8 halves / uint4
            const float4* bf4  = (const float4*)sBF;
            float acc = 0.f;
            #pragma unroll
            for (int seg = 0; seg < 16; ++seg) {      // 16 x LDG.128 per lane, high MLP
                int   g  = lane + 32 * seg;
                uint4 kv = krow[g];
                float4 b0 = bf4[2 * g];
                float4 b1 = bf4[2 * g + 1];
                float2 k0 = __half22float2(*(const __half2*)&kv.x);
                float2 k1 = __half22float2(*(const __half2*)&kv.y);
                float2 k2 = __half22float2(*(const __half2*)&kv.z);
                float2 k3 = __half22float2(*(const __half2*)&kv.w);
                acc = fmaf(k0.x, b0.x, acc); acc = fmaf(k0.y, b0.y, acc);
                acc = fmaf(k1.x, b0.z, acc); acc = fmaf(k1.y, b0.w, acc);
                acc = fmaf(k2.x, b1.x, acc); acc = fmaf(k2.y, b1.y, acc);
                acc = fmaf(k3.x, b1.z, acc); acc = fmaf(k3.y, b1.w, acc);
            }
            #pragma unroll
            for (int off = 16; off > 0; off >>= 1)
                acc += __shfl_xor_sync(0xffffffffu, acc, off);
            if (lane == 0)
                d_AF[row] = AT[row] / (1.0f + acc);
        }
        grid_sync();

        // ---------------- Phase B: column-slab sums ----------------
        for (int i = tid; i < NN; i += TB) sAF[i] = d_AF[i];
        __syncthreads();

        // lane -> (row-subgroup rsub = lane>>3, column-group g = lane&7 -> cols c0+4g..+3)
        // warp w covers rows {4w + rsub + 32*step}; per step: 4 rows x 64B coalesced.
        const int rsub = lane >> 3;
        const int g    = lane & 7;
        const __half* kbase = d_Kh + (size_t)(w * 4 + rsub) * NN + c0 + g * 4;
        float a0 = 0.f, a1 = 0.f, a2 = 0.f, a3 = 0.f;
        #pragma unroll 8
        for (int step = 0; step < NN / 32; ++step) {
            int   row = w * 4 + rsub + step * 32;
            uint2 kv  = *(const uint2*)(kbase + (size_t)step * 32 * NN);
            float af  = sAF[row];
            float2 k0 = __half22float2(*(const __half2*)&kv.x);
            float2 k1 = __half22float2(*(const __half2*)&kv.y);
            a0 = fmaf(af, k0.x, a0); a1 = fmaf(af, k0.y, a1);
            a2 = fmaf(af, k1.x, a2); a3 = fmaf(af, k1.y, a3);
        }
        // reduce over the 4 row-subgroups (lanes ^8, ^16 share the same columns)
        #pragma unroll
        for (int off = 8; off <= 16; off <<= 1) {
            a0 += __shfl_xor_sync(0xffffffffu, a0, off);
            a1 += __shfl_xor_sync(0xffffffffu, a1, off);
            a2 += __shfl_xor_sync(0xffffffffu, a2, off);
            a3 += __shfl_xor_sync(0xffffffffu, a3, off);
        }
        if (rsub == 0) {
            sPart[w * 32 + g * 4 + 0] = a0;
            sPart[w * 32 + g * 4 + 1] = a1;
            sPart[w * 32 + g * 4 + 2] = a2;
            sPart[w * 32 + g * 4 + 3] = a3;
        }
        __syncthreads();
        if (tid < 32) {                               // deterministic cross-warp reduce
            float s = 0.f;
            #pragma unroll
            for (int ww = 0; ww < 8; ++ww) s += sPart[ww * 32 + tid];
            d_BF[c0 + tid] = BT[c0 + tid] / (1.0f + s);
        }
        grid_sync();
    }

    // ---------------- Phase C: C[r][j] = param^2 * AF[r] * BF[j] (fp32 exact K) ----------------
    for (int j = tid; j < NN; j += TB) sBF[j] = d_BF[j];
    __syncthreads();
    #pragma unroll
    for (int rr = 0; rr < 4; ++rr) {
        const int row = r0 + w * 4 + rr;
        const float af = d_AF[row];
        const float4* prow = (const float4*)(param + (size_t)row * NN);
        const float4* bf4  = (const float4*)sBF;
        float4* crow = (float4*)(C + (size_t)row * NN);
        #pragma unroll 4
        for (int seg = 0; seg < 32; ++seg) {
            int idx = lane + 32 * seg;
            float4 p  = prow[idx];
            float4 bf = bf4[idx];
            float4 o;
            o.x = p.x * p.x * af * bf.x;
            o.y = p.y * p.y * af * bf.y;
            o.z = p.z * p.z * af * bf.z;
            o.w = p.w * p.w * af * bf.w;
            crow[idx] = o;
        }
    }
}

// ---------------------------------------------------------------------------
extern "C" void kernel_launch(void* const* d_in, const int* in_sizes, int n_in,
                              void* d_out, int out_size) {
    // param is the 16M-element input; AT, BT are the two 4096-element inputs in order.
    int pi = 2;
    for (int i = 0; i < n_in; ++i)
        if (in_sizes[i] == NN * NN) pi = i;
    const float* vecs[2] = {nullptr, nullptr};
    int k = 0;
    for (int i = 0; i < n_in && k < 2; ++i)
        if (i != pi) vecs[k++] = (const float*)d_in[i];
    const float* AT    = vecs[0];
    const float* BT    = vecs[1];
    const float* param = (const float*)d_in[pi];
    float* C = (float*)d_out;

    // Kh = fp16(param^2): 16,777,216 elems / (256 thr * 8 elem) = 8192 blocks exact.
    setup_kernel<<<8192, 256>>>(param);
    // Persistent solver: 128 blocks <= SM count -> all co-resident (barrier-safe).
    solve_kernel<<<GB, TB>>>(AT, BT, param, C);
}

// round 11
// speedup vs baseline: 1.0993x; 1.0993x over previous
#include <cuda_runtime.h>
#include <cuda_fp16.h>

#define NN 4096
#define ITERS 21            // 20 scan iterations + 1 last-iterate
#define GB 128              // blocks (<= SM count -> co-resident, barrier-safe)
#define TB 512              // threads per block (16 warps)
#define RPB (NN / GB)       // 32 rows per block  (phase A ownership)
#define CPB (NN / GB)       // 32 cols per block  (phase B ownership)

// ---- device-global scratch (static allocation; no cudaMalloc allowed) ----
__device__ __align__(16) __half d_Kh[(size_t)NN * NN];  // K = param^2 in fp16 (32 MB, L2-resident)
__device__ float d_AF[NN];
__device__ float d_BF[NN];
__device__ unsigned int d_bar;  // monotone grid-barrier counter

// ---------------------------------------------------------------------------
// Software grid barrier. GB (128) <= #SMs so all blocks are resident.
// __threadfence() is gpu-scope -> CCTL.IVALL on sm_103a: invalidates this
// SM's L1 so post-barrier LDGs of d_AF/d_BF see other SMs' writes (and the
// subsequent L1 reuse within the phase is of FRESH data).
// ---------------------------------------------------------------------------
__device__ __forceinline__ void grid_sync() {
    __syncthreads();
    if (threadIdx.x == 0) {
        __threadfence();                                   // release
        unsigned int nb  = gridDim.x;
        unsigned int old = atomicAdd(&d_bar, 1u);
        unsigned int gen = old - (old % nb) + nb;
        while (*((volatile unsigned int*)&d_bar) < gen) { }
        __threadfence();                                   // acquire (L1 invalidate)
    }
    __syncthreads();
}

// ---------------------------------------------------------------------------
// Setup: Kh = float2half(param^2). 8 elements/thread, exact coverage.
// ---------------------------------------------------------------------------
__global__ void setup_kernel(const float* __restrict__ param) {
    size_t base = ((size_t)blockIdx.x * blockDim.x + threadIdx.x) * 8;
    float4 p0 = *(const float4*)(param + base);
    float4 p1 = *(const float4*)(param + base + 4);
    __half2 hs[4];
    hs[0] = __floats2half2_rn(p0.x * p0.x, p0.y * p0.y);
    hs[1] = __floats2half2_rn(p0.z * p0.z, p0.w * p0.w);
    hs[2] = __floats2half2_rn(p1.x * p1.x, p1.y * p1.y);
    hs[3] = __floats2half2_rn(p1.z * p1.z, p1.w * p1.w);
    *reinterpret_cast<uint4*>(d_Kh + base) = *reinterpret_cast<uint4*>(hs);
}

// ---------------------------------------------------------------------------
// Persistent solver, 16 warps/block.
//  Phase A (rows): each warp owns 2 rows; 4 fp32 accumulators/row; K loads
//    batched 8-deep (2 rows x 4 segs) for MLP; BF read via LDG (L1-cached,
//    no smem bank conflicts).
//  Phase B (cols): warp w covers rows {4w+rsub + 64*step}; 4 cols/lane;
//    8-deep unrolled independent LDG.64; AF broadcast from smem (conflict-free).
//  Phase C: C = param^2 * AF[:,None] * BF[None,:] with exact fp32 param.
// ---------------------------------------------------------------------------
__global__ void __launch_bounds__(TB) solve_kernel(
    const float* __restrict__ AT,
    const float* __restrict__ BT,
    const float* __restrict__ param,
    float* __restrict__ C)
{
    __shared__ float sAF[NN];         // phase B: AF for broadcast reads
    __shared__ float sPart[16 * 32];  // phase B cross-warp partials

    const int tid  = threadIdx.x;
    const int lane = tid & 31;
    const int w    = tid >> 5;        // warp 0..15
    const int b    = blockIdx.x;
    const int r0   = b * RPB;
    const int c0   = b * CPB;

    for (int it = 0; it < ITERS; ++it) {
        // ---------------- Phase A: row dots (2 rows per warp) ----------------
        const float4* __restrict__ bf4 =
            (const float4*)((it == 0) ? BT : (const float*)d_BF);   // BF_0 = BT

        const int row0 = r0 + w * 2;
        const uint4* __restrict__ k0 = (const uint4*)(d_Kh + (size_t)row0 * NN);
        const uint4* __restrict__ k1 = (const uint4*)(d_Kh + (size_t)(row0 + 1) * NN);

        float acc0[4] = {0.f, 0.f, 0.f, 0.f};
        float acc1[4] = {0.f, 0.f, 0.f, 0.f};

        #pragma unroll
        for (int c = 0; c < 4; ++c) {           // 4 chunks x 4 segs = 16 segs/lane/row
            uint4  kv0[4], kv1[4];
            float4 bb[4][2];
            #pragma unroll
            for (int s = 0; s < 4; ++s) {       // batch loads: 8 K-LDG.128 + 8 BF-LDG.128 in flight
                int g = lane + 32 * (c * 4 + s);
                kv0[s]   = k0[g];
                kv1[s]   = k1[g];
                bb[s][0] = bf4[2 * g];
                bb[s][1] = bf4[2 * g + 1];
            }
            #pragma unroll
            for (int s = 0; s < 4; ++s) {
                float2 x;
                x = __half22float2(*(const __half2*)&kv0[s].x);
                acc0[s] = fmaf(x.x, bb[s][0].x, acc0[s]); acc0[s] = fmaf(x.y, bb[s][0].y, acc0[s]);
                x = __half22float2(*(const __half2*)&kv0[s].y);
                acc0[s] = fmaf(x.x, bb[s][0].z, acc0[s]); acc0[s] = fmaf(x.y, bb[s][0].w, acc0[s]);
                x = __half22float2(*(const __half2*)&kv0[s].z);
                acc0[s] = fmaf(x.x, bb[s][1].x, acc0[s]); acc0[s] = fmaf(x.y, bb[s][1].y, acc0[s]);
                x = __half22float2(*(const __half2*)&kv0[s].w);
                acc0[s] = fmaf(x.x, bb[s][1].z, acc0[s]); acc0[s] = fmaf(x.y, bb[s][1].w, acc0[s]);

                x = __half22float2(*(const __half2*)&kv1[s].x);
                acc1[s] = fmaf(x.x, bb[s][0].x, acc1[s]); acc1[s] = fmaf(x.y, bb[s][0].y, acc1[s]);
                x = __half22float2(*(const __half2*)&kv1[s].y);
                acc1[s] = fmaf(x.x, bb[s][0].z, acc1[s]); acc1[s] = fmaf(x.y, bb[s][0].w, acc1[s]);
                x = __half22float2(*(const __half2*)&kv1[s].z);
                acc1[s] = fmaf(x.x, bb[s][1].x, acc1[s]); acc1[s] = fmaf(x.y, bb[s][1].y, acc1[s]);
                x = __half22float2(*(const __half2*)&kv1[s].w);
                acc1[s] = fmaf(x.x, bb[s][1].z, acc1[s]); acc1[s] = fmaf(x.y, bb[s][1].w, acc1[s]);
            }
        }
        float a0 = (acc0[0] + acc0[1]) + (acc0[2] + acc0[3]);
        float a1 = (acc1[0] + acc1[1]) + (acc1[2] + acc1[3]);
        #pragma unroll
        for (int off = 16; off > 0; off >>= 1) {
            a0 += __shfl_xor_sync(0xffffffffu, a0, off);
            a1 += __shfl_xor_sync(0xffffffffu, a1, off);
        }
        if (lane == 0) {
            d_AF[row0]     = AT[row0]     / (1.0f + a0);
            d_AF[row0 + 1] = AT[row0 + 1] / (1.0f + a1);
        }
        grid_sync();

        // ---------------- Phase B: column-slab sums ----------------
        for (int i = tid; i < NN; i += TB) sAF[i] = d_AF[i];
        __syncthreads();

        // lane -> (rsub = lane>>3 in 0..3, colgroup g = lane&7 -> cols c0+4g..+3)
        // warp w covers rows {4w + rsub + 64*step}; per inst: 4 rows x 64B coalesced.
        const int rsub = lane >> 3;
        const int g    = lane & 7;
        const __half* kb = d_Kh + (size_t)(w * 4 + rsub) * NN + c0 + g * 4;
        float p0 = 0.f, p1 = 0.f, p2 = 0.f, p3 = 0.f;
        #pragma unroll 8
        for (int step = 0; step < NN / 64; ++step) {           // 64 steps
            int   row = w * 4 + rsub + step * 64;
            uint2 kv  = *(const uint2*)(kb + (size_t)step * 64 * NN);
            float af  = sAF[row];                               // broadcast, conflict-free
            float2 x = __half22float2(*(const __half2*)&kv.x);
            float2 y = __half22float2(*(const __half2*)&kv.y);
            p0 = fmaf(af, x.x, p0); p1 = fmaf(af, x.y, p1);
            p2 = fmaf(af, y.x, p2); p3 = fmaf(af, y.y, p3);
        }
        #pragma unroll
        for (int off = 8; off <= 16; off <<= 1) {               // fold rsub groups
            p0 += __shfl_xor_sync(0xffffffffu, p0, off);
            p1 += __shfl_xor_sync(0xffffffffu, p1, off);
            p2 += __shfl_xor_sync(0xffffffffu, p2, off);
            p3 += __shfl_xor_sync(0xffffffffu, p3, off);
        }
        if (rsub == 0) {
            sPart[w * 32 + g * 4 + 0] = p0;
            sPart[w * 32 + g * 4 + 1] = p1;
            sPart[w * 32 + g * 4 + 2] = p2;
            sPart[w * 32 + g * 4 + 3] = p3;
        }
        __syncthreads();
        if (tid < 32) {                                         // deterministic cross-warp reduce
            float s = 0.f;
            #pragma unroll
            for (int ww = 0; ww < 16; ++ww) s += sPart[ww * 32 + tid];
            d_BF[c0 + tid] = BT[c0 + tid] / (1.0f + s);
        }
        grid_sync();
    }

    // ---------------- Phase C: C[r][j] = param^2 * AF[r] * BF[j] (exact fp32 K) ----------------
    const float4* __restrict__ bfv = (const float4*)d_BF;       // L1 fresh after last grid_sync
    #pragma unroll
    for (int rr = 0; rr < 2; ++rr) {
        const int   row = r0 + w * 2 + rr;
        const float af  = d_AF[row];
        const float4* prow = (const float4*)(param + (size_t)row * NN);
        float4*       crow = (float4*)(C + (size_t)row * NN);
        #pragma unroll 4
        for (int seg = 0; seg < 32; ++seg) {
            int idx = lane + 32 * seg;
            float4 p  = prow[idx];
            float4 f  = bfv[idx];
            float4 o;
            o.x = p.x * p.x * af * f.x;
            o.y = p.y * p.y * af * f.y;
            o.z = p.z * p.z * af * f.z;
            o.w = p.w * p.w * af * f.w;
            crow[idx] = o;
        }
    }
}

// ---------------------------------------------------------------------------
extern "C" void kernel_launch(void* const* d_in, const int* in_sizes, int n_in,
                              void* d_out, int out_size) {
    // param is the 16M-element input; AT, BT are the two 4096-element inputs in order.
    int pi = 2;
    for (int i = 0; i < n_in; ++i)
        if (in_sizes[i] == NN * NN) pi = i;
    const float* vecs[2] = {nullptr, nullptr};
    int k = 0;
    for (int i = 0; i < n_in && k < 2; ++i)
        if (i != pi) vecs[k++] = (const float*)d_in[i];
    const float* AT    = vecs[0];
    const float* BT    = vecs[1];
    const float* param = (const float*)d_in[pi];
    float* C = (float*)d_out;

    // Kh = fp16(param^2): 16,777,216 / (256*8) = 8192 blocks exact.
    setup_kernel<<<8192, 256>>>(param);
    // Persistent solver: 128 blocks <= SM count -> all co-resident (barrier-safe).
    solve_kernel<<<GB, TB>>>(AT, BT, param, C);
}